// round 1
// baseline (speedup 1.0000x reference)
#include <cuda_runtime.h>
#include <cstdint>
#include <math.h>

// Problem constants (from reference)
#define D        10      // EMBEDDING_DIM
#define NUMF     16      // NUM_NUMERIC
#define DIN      36      // 2*D + NUMF
#define H        128     // hidden
#define CS1      1
#define CS2      3
#define RPB      256     // rows per block
#define THREADS  256

// token windows staged per block
#define E1_TOK (RPB + 2*CS1)   // 258
#define E2_TOK (RPB + 2*CS2)   // 262
#define EPAD   11              // shared row stride (odd -> conflict free)

// ---------- packed f32x2 helpers (Blackwell) ----------
__device__ __forceinline__ unsigned long long pack2(float a, float b) {
    unsigned long long r;
    asm("mov.b64 %0, {%1, %2};" : "=l"(r) : "f"(a), "f"(b));
    return r;
}
__device__ __forceinline__ void unpack2(unsigned long long p, float& a, float& b) {
    asm("mov.b64 {%0, %1}, %2;" : "=f"(a), "=f"(b) : "l"(p));
}
__device__ __forceinline__ void fma2(unsigned long long& acc,
                                     unsigned long long a, unsigned long long b) {
    asm("fma.rn.f32x2 %0, %1, %2, %0;" : "+l"(acc) : "l"(a), "l"(b));
}
__device__ __forceinline__ unsigned long long add2(unsigned long long a, unsigned long long b) {
    unsigned long long r;
    asm("add.rn.f32x2 %0, %1, %2;" : "=l"(r) : "l"(a), "l"(b));
    return r;
}

__global__ void wordemb_fused_kernel(
    const int*   __restrict__ t1,
    const int*   __restrict__ t2,
    const float* __restrict__ numf,
    const float* __restrict__ T1,
    const float* __restrict__ T2,
    const float* __restrict__ W1,   // [36][128] row-major
    const float* __restrict__ b1,   // [128]
    const float* __restrict__ W2,   // [128][1]
    const float* __restrict__ b2,   // [1]
    float* __restrict__ out,        // [N]
    int n)
{
    __shared__ __align__(16) float s_w1[H * DIN];   // transposed: [j][k], 144B rows (16B aligned)
    __shared__ float s_b1[H];
    __shared__ float s_w2[H];
    __shared__ float s_e1[E1_TOK * EPAD];
    __shared__ float s_e2[E2_TOK * EPAD];
    __shared__ int   s_tok1[E1_TOK];
    __shared__ int   s_tok2[E2_TOK];

    const int tid = threadIdx.x;
    const int r0  = blockIdx.x * RPB;

    // ---- stage token ids (clamped windows: OOB rows marked -1 -> zero embedding) ----
    for (int r = tid; r < E1_TOK; r += THREADS) {
        int g = r0 - CS1 + r;
        s_tok1[r] = (g >= 0 && g < n) ? t1[g] : -1;
    }
    for (int r = tid; r < E2_TOK; r += THREADS) {
        int g = r0 - CS2 + r;
        s_tok2[r] = (g >= 0 && g < n) ? t2[g] : -1;
    }
    // ---- W1 transpose into shared (coalesced global read, scattered smem write) ----
    for (int idx = tid; idx < H * DIN; idx += THREADS) {
        int k = idx >> 7;        // idx / 128
        int j = idx & 127;       // idx % 128
        s_w1[j * DIN + k] = W1[idx];
    }
    if (tid < H) { s_b1[tid] = b1[tid]; s_w2[tid] = W2[tid]; }
    __syncthreads();

    // ---- gather embeddings for staged tokens (tables live in L2: 2MB each) ----
    for (int e = tid; e < E1_TOK * D; e += THREADS) {
        int r = e / D, d = e - r * D;
        int tok = s_tok1[r];
        s_e1[r * EPAD + d] = (tok >= 0) ? T1[tok * D + d] : 0.0f;
    }
    for (int e = tid; e < E2_TOK * D; e += THREADS) {
        int r = e / D, d = e - r * D;
        int tok = s_tok2[r];
        s_e2[r * EPAD + d] = (tok >= 0) ? T2[tok * D + d] : 0.0f;
    }
    __syncthreads();

    const int i = r0 + tid;
    if (i >= n) return;

    // ---- build x[36]: contextual means + numeric ----
    float x[DIN];
    {
        int lo1 = max(i - CS1, 0), hi1 = min(i + CS1 + 1, n);
        float inv1 = 1.0f / (float)(hi1 - lo1);
        int lo2 = max(i - CS2, 0), hi2 = min(i + CS2 + 1, n);
        float inv2 = 1.0f / (float)(hi2 - lo2);
        // e1: window of 3 (smem rows tid .. tid+2 correspond to i-1 .. i+1)
        #pragma unroll
        for (int d = 0; d < D; d++) {
            float s = s_e1[(tid + 0) * EPAD + d]
                    + s_e1[(tid + 1) * EPAD + d]
                    + s_e1[(tid + 2) * EPAD + d];
            x[d] = s * inv1;
        }
        // e2: window of 7 (smem rows tid .. tid+6 correspond to i-3 .. i+3)
        #pragma unroll
        for (int d = 0; d < D; d++) {
            float s = 0.0f;
            #pragma unroll
            for (int w = 0; w < 7; w++) s += s_e2[(tid + w) * EPAD + d];
            x[D + d] = s * inv2;
        }
        // numeric features: 64B per row, vectorized
        const float4* nf = reinterpret_cast<const float4*>(numf) + (size_t)i * (NUMF / 4);
        #pragma unroll
        for (int q = 0; q < 4; q++) {
            float4 v = nf[q];
            x[2 * D + 4 * q + 0] = v.x;
            x[2 * D + 4 * q + 1] = v.y;
            x[2 * D + 4 * q + 2] = v.z;
            x[2 * D + 4 * q + 3] = v.w;
        }
    }

    // ---- pack x into 18 f32x2 registers ----
    unsigned long long x2[DIN / 2];
    #pragma unroll
    for (int p = 0; p < DIN / 2; p++) x2[p] = pack2(x[2 * p], x[2 * p + 1]);

    // ---- fused MLP: h = relu(x@W1+b1); acc = h@W2 + b2 ----
    float acc = b2[0];
    #pragma unroll 2
    for (int j = 0; j < H; j++) {
        const ulonglong2* wj = reinterpret_cast<const ulonglong2*>(&s_w1[j * DIN]);
        unsigned long long p0 = 0ull, p1 = 0ull;  // bit pattern 0 == (0.0f, 0.0f)
        #pragma unroll
        for (int q = 0; q < 9; q++) {
            ulonglong2 w = wj[q];                 // LDS.128: W1[j][4q .. 4q+3]
            fma2(p0, x2[2 * q + 0], w.x);
            fma2(p1, x2[2 * q + 1], w.y);
        }
        float a, b;
        unpack2(add2(p0, p1), a, b);
        float h = (a + b) + s_b1[j];
        h = fmaxf(h, 0.0f);
        acc = fmaf(h, s_w2[j], acc);
    }

    out[i] = 1.0f / (1.0f + expf(-acc));
}

extern "C" void kernel_launch(void* const* d_in, const int* in_sizes, int n_in,
                              void* d_out, int out_size) {
    const int*   t1   = (const int*)d_in[0];
    const int*   t2   = (const int*)d_in[1];
    const float* numf = (const float*)d_in[2];
    const float* T1   = (const float*)d_in[3];
    const float* T2   = (const float*)d_in[4];
    const float* W1   = (const float*)d_in[5];
    const float* b1   = (const float*)d_in[6];
    const float* W2   = (const float*)d_in[7];
    const float* b2   = (const float*)d_in[8];
    float* out = (float*)d_out;

    int n = in_sizes[0];
    int blocks = (n + RPB - 1) / RPB;
    wordemb_fused_kernel<<<blocks, THREADS>>>(t1, t2, numf, T1, T2, W1, b1, W2, b2, out, n);
}

// round 3
// speedup vs baseline: 1.2647x; 1.2647x over previous
#include <cuda_runtime.h>
#include <cstdint>
#include <math.h>

#define D        10      // EMBEDDING_DIM
#define NUMF     16      // NUM_NUMERIC
#define DIN      36      // 2*D + NUMF
#define H        128     // hidden
#define CS1      1
#define CS2      3
#define RPB      256     // rows per block (2 per thread)
#define THREADS  128

#define E1_TOK (RPB + 2*CS1)   // 258
#define E2_TOK (RPB + 2*CS2)   // 262
#define EPAD   11              // shared row stride (odd -> low conflict)

// ---------- packed f32x2 helpers (Blackwell) ----------
__device__ __forceinline__ unsigned long long pack2(float a, float b) {
    unsigned long long r;
    asm("mov.b64 %0, {%1, %2};" : "=l"(r) : "f"(a), "f"(b));
    return r;
}
__device__ __forceinline__ void unpack2(unsigned long long p, float& a, float& b) {
    asm("mov.b64 {%0, %1}, %2;" : "=f"(a), "=f"(b) : "l"(p));
}
__device__ __forceinline__ void fma2(unsigned long long& acc,
                                     unsigned long long a, unsigned long long b) {
    asm("fma.rn.f32x2 %0, %1, %2, %0;" : "+l"(acc) : "l"(a), "l"(b));
}
__device__ __forceinline__ unsigned long long add2(unsigned long long a, unsigned long long b) {
    unsigned long long r;
    asm("add.rn.f32x2 %0, %1, %2;" : "=l"(r) : "l"(a), "l"(b));
    return r;
}

__global__ __launch_bounds__(THREADS, 4)
void wordemb_r2_kernel(
    const int*   __restrict__ t1,
    const int*   __restrict__ t2,
    const float* __restrict__ numf,
    const float* __restrict__ T1,
    const float* __restrict__ T2,
    const float* __restrict__ W1,   // [36][128] row-major
    const float* __restrict__ b1,   // [128]
    const float* __restrict__ W2,   // [128]
    const float* __restrict__ b2,   // [1]
    float* __restrict__ out,        // [N]
    int n)
{
    __shared__ __align__(16) float s_w1[H * DIN];   // transposed: [j][k], 144B rows
    __shared__ float2 s_bw[H];                      // {b1[j], w2[j]}
    __shared__ float s_e1[E1_TOK * EPAD];
    __shared__ float s_e2[E2_TOK * EPAD];
    __shared__ int   s_tok1[E1_TOK];
    __shared__ int   s_tok2[E2_TOK];

    const int tid = threadIdx.x;
    const int r0  = blockIdx.x * RPB;

    // ---- stage token ids (clamped windows; OOB -> -1 -> zero embedding) ----
    for (int r = tid; r < E1_TOK; r += THREADS) {
        int g = r0 - CS1 + r;
        s_tok1[r] = (g >= 0 && g < n) ? t1[g] : -1;
    }
    for (int r = tid; r < E2_TOK; r += THREADS) {
        int g = r0 - CS2 + r;
        s_tok2[r] = (g >= 0 && g < n) ? t2[g] : -1;
    }
    // ---- W1 transpose into shared ----
    for (int idx = tid; idx < H * DIN; idx += THREADS) {
        int k = idx >> 7;        // idx / 128
        int j = idx & 127;       // idx % 128
        s_w1[j * DIN + k] = W1[idx];
    }
    if (tid < H) s_bw[tid] = make_float2(b1[tid], W2[tid]);
    __syncthreads();

    // ---- gather embeddings for staged tokens ----
    for (int e = tid; e < E1_TOK * D; e += THREADS) {
        int r = e / D, d = e - r * D;
        int tok = s_tok1[r];
        s_e1[r * EPAD + d] = (tok >= 0) ? T1[tok * D + d] : 0.0f;
    }
    for (int e = tid; e < E2_TOK * D; e += THREADS) {
        int r = e / D, d = e - r * D;
        int tok = s_tok2[r];
        s_e2[r * EPAD + d] = (tok >= 0) ? T2[tok * D + d] : 0.0f;
    }
    __syncthreads();

    const int a = r0 + 2 * tid;      // first row of this thread's pair
    const int bq = a + 1;            // second row

    // ---- build x for both rows (sliding-window sharing) ----
    float xa[DIN], xb[DIN];
    {
        int lo1a = max(a - CS1, 0),  hi1a = min(a + CS1 + 1, n);
        int lo1b = max(bq - CS1, 0), hi1b = min(bq + CS1 + 1, n);
        int lo2a = max(a - CS2, 0),  hi2a = min(a + CS2 + 1, n);
        int lo2b = max(bq - CS2, 0), hi2b = min(bq + CS2 + 1, n);
        float inv1a = __fdividef(1.0f, (float)max(hi1a - lo1a, 1));
        float inv1b = __fdividef(1.0f, (float)max(hi1b - lo1b, 1));
        float inv2a = __fdividef(1.0f, (float)max(hi2a - lo2a, 1));
        float inv2b = __fdividef(1.0f, (float)max(hi2b - lo2b, 1));

        const int s1 = 2 * tid;   // smem index of row (a - CS1)
        #pragma unroll
        for (int d = 0; d < D; d++) {
            float e0 = s_e1[(s1 + 0) * EPAD + d];
            float e1v = s_e1[(s1 + 1) * EPAD + d];
            float e2v = s_e1[(s1 + 2) * EPAD + d];
            float e3v = s_e1[(s1 + 3) * EPAD + d];
            float sA = e0 + e1v + e2v;
            xa[d] = sA * inv1a;
            xb[d] = (sA - e0 + e3v) * inv1b;
        }
        const int s2 = 2 * tid;   // smem index of row (a - CS2)
        #pragma unroll
        for (int d = 0; d < D; d++) {
            float v0 = s_e2[(s2 + 0) * EPAD + d];
            float sA = v0;
            #pragma unroll
            for (int w = 1; w < 7; w++) sA += s_e2[(s2 + w) * EPAD + d];
            float v7 = s_e2[(s2 + 7) * EPAD + d];
            xa[D + d] = sA * inv2a;
            xb[D + d] = (sA - v0 + v7) * inv2b;
        }
        // numeric features: 128B contiguous per thread (rows a, a+1)
        if (bq < n) {
            const float4* nf = reinterpret_cast<const float4*>(numf) + (size_t)a * (NUMF / 4);
            #pragma unroll
            for (int q = 0; q < 4; q++) {
                float4 v = nf[q];
                xa[2*D + 4*q + 0] = v.x; xa[2*D + 4*q + 1] = v.y;
                xa[2*D + 4*q + 2] = v.z; xa[2*D + 4*q + 3] = v.w;
            }
            #pragma unroll
            for (int q = 0; q < 4; q++) {
                float4 v = nf[4 + q];
                xb[2*D + 4*q + 0] = v.x; xb[2*D + 4*q + 1] = v.y;
                xb[2*D + 4*q + 2] = v.z; xb[2*D + 4*q + 3] = v.w;
            }
        } else if (a < n) {
            const float4* nf = reinterpret_cast<const float4*>(numf) + (size_t)a * (NUMF / 4);
            #pragma unroll
            for (int q = 0; q < 4; q++) {
                float4 v = nf[q];
                xa[2*D + 4*q + 0] = v.x; xa[2*D + 4*q + 1] = v.y;
                xa[2*D + 4*q + 2] = v.z; xa[2*D + 4*q + 3] = v.w;
            }
            #pragma unroll
            for (int q = 0; q < NUMF; q++) xb[2*D + q] = 0.0f;
        } else {
            #pragma unroll
            for (int q = 0; q < NUMF; q++) { xa[2*D + q] = 0.0f; xb[2*D + q] = 0.0f; }
        }
    }

    // ---- pack both rows into f32x2 registers ----
    unsigned long long xa2[DIN / 2], xb2[DIN / 2];
    #pragma unroll
    for (int p = 0; p < DIN / 2; p++) {
        xa2[p] = pack2(xa[2*p], xa[2*p + 1]);
        xb2[p] = pack2(xb[2*p], xb[2*p + 1]);
    }

    // ---- fused MLP for 2 rows: one W1 read serves 4 FFMA2 chains ----
    const float b2v = b2[0];
    float acc_a = b2v, acc_b = b2v;
    #pragma unroll 4
    for (int j = 0; j < H; j++) {
        const ulonglong2* wj = reinterpret_cast<const ulonglong2*>(&s_w1[j * DIN]);
        unsigned long long pa0 = 0ull, pa1 = 0ull, pb0 = 0ull, pb1 = 0ull;
        #pragma unroll
        for (int q = 0; q < 9; q++) {
            ulonglong2 w = wj[q];             // LDS.128 broadcast: W1[j][4q..4q+3]
            fma2(pa0, xa2[2*q + 0], w.x);
            fma2(pa1, xa2[2*q + 1], w.y);
            fma2(pb0, xb2[2*q + 0], w.x);
            fma2(pb1, xb2[2*q + 1], w.y);
        }
        float2 bw = s_bw[j];                  // {b1[j], w2[j]}
        float u0, u1, v0, v1;
        unpack2(add2(pa0, pa1), u0, u1);
        unpack2(add2(pb0, pb1), v0, v1);
        float ha = fmaxf((u0 + u1) + bw.x, 0.0f);
        float hb = fmaxf((v0 + v1) + bw.x, 0.0f);
        acc_a = fmaf(ha, bw.y, acc_a);
        acc_b = fmaf(hb, bw.y, acc_b);
    }

    float sig_a = __fdividef(1.0f, 1.0f + __expf(-acc_a));
    float sig_b = __fdividef(1.0f, 1.0f + __expf(-acc_b));

    if (bq < n) {
        reinterpret_cast<float2*>(out)[a >> 1] = make_float2(sig_a, sig_b);
    } else if (a < n) {
        out[a] = sig_a;
    }
}

extern "C" void kernel_launch(void* const* d_in, const int* in_sizes, int n_in,
                              void* d_out, int out_size) {
    const int*   t1   = (const int*)d_in[0];
    const int*   t2   = (const int*)d_in[1];
    const float* numf = (const float*)d_in[2];
    const float* T1   = (const float*)d_in[3];
    const float* T2   = (const float*)d_in[4];
    const float* W1   = (const float*)d_in[5];
    const float* b1   = (const float*)d_in[6];
    const float* W2   = (const float*)d_in[7];
    const float* b2   = (const float*)d_in[8];
    float* out = (float*)d_out;

    int n = in_sizes[0];
    int blocks = (n + RPB - 1) / RPB;
    wordemb_r2_kernel<<<blocks, THREADS>>>(t1, t2, numf, T1, T2, W1, b1, W2, b2, out, n);
}

// round 4
// speedup vs baseline: 1.8638x; 1.4737x over previous
#include <cuda_runtime.h>
#include <cuda_bf16.h>
#include <cstdint>
#include <math.h>

#define D        10
#define NUMF     16
#define DIN      36       // 2*D + NUMF
#define KTOT     48       // padded K (37 used: 36 features + bias channel)
#define H        128
#define CS1      1
#define CS2      3
#define TILE_M   128
#define THREADS  128

#define E1_TOK (TILE_M + 2*CS1)   // 130
#define E2_TOK (TILE_M + 2*CS2)   // 134
#define EPAD   11
#define SA     116                 // A row stride in bytes (29 banks: conflict-free)

__device__ __forceinline__ uint32_t bf16pair(float a, float b) {
    __nv_bfloat16 ha = __float2bfloat16_rn(a), hb = __float2bfloat16_rn(b);
    return (uint32_t)__bfloat16_as_ushort(ha) | ((uint32_t)__bfloat16_as_ushort(hb) << 16);
}

__device__ __forceinline__ void mma_bf16(float d[4],
                                         uint32_t a0, uint32_t a1, uint32_t a2, uint32_t a3,
                                         uint32_t b0, uint32_t b1) {
    asm volatile(
        "mma.sync.aligned.m16n8k16.row.col.f32.bf16.bf16.f32 "
        "{%0,%1,%2,%3}, {%4,%5,%6,%7}, {%8,%9}, {%0,%1,%2,%3};"
        : "+f"(d[0]), "+f"(d[1]), "+f"(d[2]), "+f"(d[3])
        : "r"(a0), "r"(a1), "r"(a2), "r"(a3), "r"(b0), "r"(b1));
}

__global__ __launch_bounds__(THREADS, 4)
void wordemb_mma_kernel(
    const int*   __restrict__ t1,
    const int*   __restrict__ t2,
    const float* __restrict__ numf,
    const float* __restrict__ T1,
    const float* __restrict__ T2,
    const float* __restrict__ W1,   // [36][128] row-major
    const float* __restrict__ b1,   // [128]
    const float* __restrict__ W2,   // [128]
    const float* __restrict__ b2,   // [1]
    float* __restrict__ out,
    int n)
{
    __shared__ __align__(16) char  s_Ahi[TILE_M * SA];
    __shared__ __align__(16) char  s_Alo[TILE_M * SA];
    __shared__ float s_e1[E1_TOK * EPAD];
    __shared__ float s_e2[E2_TOK * EPAD];
    __shared__ int   s_tok1[E1_TOK];
    __shared__ int   s_tok2[E2_TOK];
    __shared__ float s_part[4][TILE_M];

    const int tid  = threadIdx.x;
    const int wid  = tid >> 5;
    const int lane = tid & 31;
    const int r0g  = blockIdx.x * TILE_M;
    const int i    = r0g + tid;

    // ================= Phase 1: stage tokens, gather, build x, write A =================
    for (int r = tid; r < E1_TOK; r += THREADS) {
        int g = r0g - CS1 + r;
        s_tok1[r] = (g >= 0 && g < n) ? t1[g] : -1;
    }
    for (int r = tid; r < E2_TOK; r += THREADS) {
        int g = r0g - CS2 + r;
        s_tok2[r] = (g >= 0 && g < n) ? t2[g] : -1;
    }
    __syncthreads();

    for (int e = tid; e < E1_TOK * D; e += THREADS) {
        int r = e / D, d = e - r * D;
        int tok = s_tok1[r];
        s_e1[r * EPAD + d] = (tok >= 0) ? T1[tok * D + d] : 0.0f;
    }
    for (int e = tid; e < E2_TOK * D; e += THREADS) {
        int r = e / D, d = e - r * D;
        int tok = s_tok2[r];
        s_e2[r * EPAD + d] = (tok >= 0) ? T2[tok * D + d] : 0.0f;
    }
    __syncthreads();

    {
        float x[KTOT];
        int lo1 = max(i - CS1, 0), hi1 = min(i + CS1 + 1, n);
        int lo2 = max(i - CS2, 0), hi2 = min(i + CS2 + 1, n);
        float inv1 = __fdividef(1.0f, (float)max(hi1 - lo1, 1));
        float inv2 = __fdividef(1.0f, (float)max(hi2 - lo2, 1));
        #pragma unroll
        for (int d = 0; d < D; d++) {
            float s = s_e1[(tid + 0) * EPAD + d] + s_e1[(tid + 1) * EPAD + d]
                    + s_e1[(tid + 2) * EPAD + d];
            x[d] = s * inv1;
        }
        #pragma unroll
        for (int d = 0; d < D; d++) {
            float s = 0.0f;
            #pragma unroll
            for (int w = 0; w < 7; w++) s += s_e2[(tid + w) * EPAD + d];
            x[D + d] = s * inv2;
        }
        if (i < n) {
            const float4* nf = reinterpret_cast<const float4*>(numf) + (size_t)i * (NUMF / 4);
            #pragma unroll
            for (int q = 0; q < 4; q++) {
                float4 v = nf[q];
                x[2*D + 4*q + 0] = v.x; x[2*D + 4*q + 1] = v.y;
                x[2*D + 4*q + 2] = v.z; x[2*D + 4*q + 3] = v.w;
            }
        } else {
            #pragma unroll
            for (int q = 0; q < NUMF; q++) x[2*D + q] = 0.0f;
        }
        x[36] = 1.0f;   // bias channel
        #pragma unroll
        for (int k = 37; k < KTOT; k++) x[k] = 0.0f;

        // write Ahi/Alo row tid (48 bf16 = 24 u32 each)
        char* rowh = s_Ahi + tid * SA;
        char* rowl = s_Alo + tid * SA;
        #pragma unroll
        for (int q = 0; q < KTOT / 2; q++) {
            float a = x[2*q], b = x[2*q + 1];
            __nv_bfloat16 ah = __float2bfloat16_rn(a), bh = __float2bfloat16_rn(b);
            float ar = a - __bfloat162float(ah), br = b - __bfloat162float(bh);
            *reinterpret_cast<uint32_t*>(rowh + 4*q) =
                (uint32_t)__bfloat16_as_ushort(ah) | ((uint32_t)__bfloat16_as_ushort(bh) << 16);
            *reinterpret_cast<uint32_t*>(rowl + 4*q) = bf16pair(ar, br);
        }
    }

    // ================= Build constant B fragments in registers =================
    // B frag (m16n8k16.col): thread lane: n = wn0 + j*8 + (lane>>2), k0 = (lane&3)*2
    // b0 = {W(k0,n), W(k0+1,n)}, b1 = {W(k0+8,n), W(k0+9,n)}
    uint32_t Bhi[4][3][2], Blo[4][3][2];
    float w2r[4][2];
    {
        const int nsub = lane >> 2;
        const int ksub = (lane & 3) * 2;
        #pragma unroll
        for (int j = 0; j < 4; j++) {
            int nn = wid * 32 + j * 8 + nsub;
            #pragma unroll
            for (int s = 0; s < 3; s++) {
                #pragma unroll
                for (int half = 0; half < 2; half++) {
                    int k0 = s * 16 + ksub + half * 8;
                    float wv0, wv1;
                    wv0 = (k0     < DIN) ? W1[k0 * H + nn]       : ((k0     == DIN) ? b1[nn] : 0.0f);
                    wv1 = (k0 + 1 < DIN) ? W1[(k0 + 1) * H + nn] : ((k0 + 1 == DIN) ? b1[nn] : 0.0f);
                    __nv_bfloat16 h0 = __float2bfloat16_rn(wv0), h1 = __float2bfloat16_rn(wv1);
                    float r0 = wv0 - __bfloat162float(h0), r1 = wv1 - __bfloat162float(h1);
                    Bhi[j][s][half] = (uint32_t)__bfloat16_as_ushort(h0)
                                    | ((uint32_t)__bfloat16_as_ushort(h1) << 16);
                    Blo[j][s][half] = bf16pair(r0, r1);
                }
            }
            // w2 for this thread's D columns: c = (lane&3)*2 + {0,1} in n-tile j
            int nc = wid * 32 + j * 8 + (lane & 3) * 2;
            w2r[j][0] = W2[nc];
            w2r[j][1] = W2[nc + 1];
        }
    }
    const float b2v = b2[0];
    __syncthreads();

    // ================= Phase 2: MMA over 8 m-tiles =================
    const int arow = lane >> 2;           // A-frag row within m-tile
    const int acol = (lane & 3) * 4;      // byte offset of k-pair within k-step

    #pragma unroll
    for (int mt = 0; mt < 8; mt++) {
        float Dacc[4][4];
        #pragma unroll
        for (int j = 0; j < 4; j++) {
            Dacc[j][0] = 0.0f; Dacc[j][1] = 0.0f; Dacc[j][2] = 0.0f; Dacc[j][3] = 0.0f;
        }
        const int rbase = mt * 16 + arow;

        #pragma unroll
        for (int s = 0; s < 3; s++) {
            const int cb = s * 32 + acol;
            uint32_t ah0 = *reinterpret_cast<const uint32_t*>(s_Ahi + rbase * SA + cb);
            uint32_t ah1 = *reinterpret_cast<const uint32_t*>(s_Ahi + (rbase + 8) * SA + cb);
            uint32_t ah2 = *reinterpret_cast<const uint32_t*>(s_Ahi + rbase * SA + cb + 16);
            uint32_t ah3 = *reinterpret_cast<const uint32_t*>(s_Ahi + (rbase + 8) * SA + cb + 16);
            uint32_t al0 = *reinterpret_cast<const uint32_t*>(s_Alo + rbase * SA + cb);
            uint32_t al1 = *reinterpret_cast<const uint32_t*>(s_Alo + (rbase + 8) * SA + cb);
            uint32_t al2 = *reinterpret_cast<const uint32_t*>(s_Alo + rbase * SA + cb + 16);
            uint32_t al3 = *reinterpret_cast<const uint32_t*>(s_Alo + (rbase + 8) * SA + cb + 16);

            #pragma unroll
            for (int j = 0; j < 4; j++)
                mma_bf16(Dacc[j], ah0, ah1, ah2, ah3, Bhi[j][s][0], Bhi[j][s][1]);
            #pragma unroll
            for (int j = 0; j < 4; j++)
                mma_bf16(Dacc[j], ah0, ah1, ah2, ah3, Blo[j][s][0], Blo[j][s][1]);
            #pragma unroll
            for (int j = 0; j < 4; j++)
                mma_bf16(Dacc[j], al0, al1, al2, al3, Bhi[j][s][0], Bhi[j][s][1]);
        }

        // epilogue: partial dot with w2 over this warp's 32 columns
        float p0 = 0.0f, p1 = 0.0f;
        #pragma unroll
        for (int j = 0; j < 4; j++) {
            p0 = fmaf(fmaxf(Dacc[j][0], 0.0f), w2r[j][0], p0);
            p0 = fmaf(fmaxf(Dacc[j][1], 0.0f), w2r[j][1], p0);
            p1 = fmaf(fmaxf(Dacc[j][2], 0.0f), w2r[j][0], p1);
            p1 = fmaf(fmaxf(Dacc[j][3], 0.0f), w2r[j][1], p1);
        }
        p0 += __shfl_xor_sync(0xFFFFFFFF, p0, 1);
        p0 += __shfl_xor_sync(0xFFFFFFFF, p0, 2);
        p1 += __shfl_xor_sync(0xFFFFFFFF, p1, 1);
        p1 += __shfl_xor_sync(0xFFFFFFFF, p1, 2);
        if ((lane & 3) == 0) {
            s_part[wid][rbase]     = p0;
            s_part[wid][rbase + 8] = p1;
        }
    }
    __syncthreads();

    // ================= Final: sum 4 warp partials, sigmoid, store =================
    if (i < n) {
        float s = s_part[0][tid] + s_part[1][tid] + s_part[2][tid] + s_part[3][tid] + b2v;
        out[i] = __fdividef(1.0f, 1.0f + __expf(-s));
    }
}

extern "C" void kernel_launch(void* const* d_in, const int* in_sizes, int n_in,
                              void* d_out, int out_size) {
    const int*   t1   = (const int*)d_in[0];
    const int*   t2   = (const int*)d_in[1];
    const float* numf = (const float*)d_in[2];
    const float* T1   = (const float*)d_in[3];
    const float* T2   = (const float*)d_in[4];
    const float* W1   = (const float*)d_in[5];
    const float* b1   = (const float*)d_in[6];
    const float* W2   = (const float*)d_in[7];
    const float* b2   = (const float*)d_in[8];
    float* out = (float*)d_out;

    int n = in_sizes[0];
    int blocks = (n + TILE_M - 1) / TILE_M;
    wordemb_mma_kernel<<<blocks, THREADS>>>(t1, t2, numf, T1, T2, W1, b1, W2, b2, out, n);
}

// round 5
// speedup vs baseline: 2.6236x; 1.4077x over previous
#include <cuda_runtime.h>
#include <cuda_bf16.h>
#include <cstdint>
#include <math.h>

#define D        10
#define NUMF     16
#define DIN      36       // 2*D + NUMF
#define H        128
#define CS1      1
#define CS2      3
#define TILE_M   128
#define THREADS  128

#define E1_TOK (TILE_M + 2*CS1)   // 130
#define E2_TOK (TILE_M + 2*CS2)   // 134
#define EPAD   11
#define SA     116                 // A row stride bytes (29 banks, conflict-free)

__device__ __forceinline__ uint32_t bf16pair(float a, float b) {
    __nv_bfloat16 ha = __float2bfloat16_rn(a), hb = __float2bfloat16_rn(b);
    return (uint32_t)__bfloat16_as_ushort(ha) | ((uint32_t)__bfloat16_as_ushort(hb) << 16);
}

__device__ __forceinline__ void split_pair(float a, float b, uint32_t& hi, uint32_t& lo) {
    __nv_bfloat16 ha = __float2bfloat16_rn(a), hb = __float2bfloat16_rn(b);
    hi = (uint32_t)__bfloat16_as_ushort(ha) | ((uint32_t)__bfloat16_as_ushort(hb) << 16);
    lo = bf16pair(a - __bfloat162float(ha), b - __bfloat162float(hb));
}

__device__ __forceinline__ void mma16(float d[4],
                                      uint32_t a0, uint32_t a1, uint32_t a2, uint32_t a3,
                                      uint32_t b0, uint32_t b1) {
    asm volatile(
        "mma.sync.aligned.m16n8k16.row.col.f32.bf16.bf16.f32 "
        "{%0,%1,%2,%3}, {%4,%5,%6,%7}, {%8,%9}, {%0,%1,%2,%3};"
        : "+f"(d[0]), "+f"(d[1]), "+f"(d[2]), "+f"(d[3])
        : "r"(a0), "r"(a1), "r"(a2), "r"(a3), "r"(b0), "r"(b1));
}
__device__ __forceinline__ void mma8(float d[4],
                                     uint32_t a0, uint32_t a1, uint32_t b0) {
    asm volatile(
        "mma.sync.aligned.m16n8k8.row.col.f32.bf16.bf16.f32 "
        "{%0,%1,%2,%3}, {%4,%5}, {%6}, {%0,%1,%2,%3};"
        : "+f"(d[0]), "+f"(d[1]), "+f"(d[2]), "+f"(d[3])
        : "r"(a0), "r"(a1), "r"(b0));
}

__global__ __launch_bounds__(THREADS, 5)
void wordemb_mma_gs_kernel(
    const int*   __restrict__ t1,
    const int*   __restrict__ t2,
    const float* __restrict__ numf,
    const float* __restrict__ T1,
    const float* __restrict__ T2,
    const float* __restrict__ W1,   // [36][128]
    const float* __restrict__ b1,   // [128]
    const float* __restrict__ W2,   // [128]
    const float* __restrict__ b2,   // [1]
    float* __restrict__ out,
    int n, int nTiles)
{
    __shared__ __align__(16) char  s_Ahi[TILE_M * SA];
    __shared__ __align__(16) char  s_Alo[TILE_M * SA];
    __shared__ float s_e1[E1_TOK * EPAD];
    __shared__ float s_e2[E2_TOK * EPAD];
    __shared__ int   s_tok1[E1_TOK];
    __shared__ int   s_tok2[E2_TOK];
    __shared__ float s_part[4][TILE_M];

    const int tid  = threadIdx.x;
    const int wid  = tid >> 5;
    const int lane = tid & 31;

    // ========== B fragments, built ONCE per block ==========
    // pos p: 0:(k0=ksub) 1:(ksub+8) 2:(16+ksub) 3:(24+ksub) 4:(32+ksub)
    // frag value = {W(k0,nn), W(k0+1,nn)}; bias channel at k==36 -> b1[nn]
    uint32_t Bhi[4][5], Blo[4][5];
    float w2r[4][2];
    {
        const int nsub = lane >> 2;
        const int ksub = (lane & 3) * 2;
        #pragma unroll
        for (int j = 0; j < 4; j++) {
            int nn = wid * 32 + j * 8 + nsub;
            #pragma unroll
            for (int p = 0; p < 5; p++) {
                int k0 = p * 8 + ksub;
                float wv0 = (k0     < DIN) ? W1[k0 * H + nn]     : ((k0     == DIN) ? b1[nn] : 0.0f);
                float wv1 = (k0 + 1 < DIN) ? W1[(k0 + 1)*H + nn] : ((k0 + 1 == DIN) ? b1[nn] : 0.0f);
                split_pair(wv0, wv1, Bhi[j][p], Blo[j][p]);
            }
            int nc = wid * 32 + j * 8 + (lane & 3) * 2;
            w2r[j][0] = W2[nc];
            w2r[j][1] = W2[nc + 1];
        }
    }
    const float b2v = b2[0];
    const float2* T1f2 = reinterpret_cast<const float2*>(T1);
    const float2* T2f2 = reinterpret_cast<const float2*>(T2);

    const int arow = lane >> 2;
    const int acol = (lane & 3) * 4;

    // ========== grid-stride over tiles ==========
    for (int tile = blockIdx.x; tile < nTiles; tile += gridDim.x) {
        const int r0g = tile * TILE_M;
        const int i   = r0g + tid;

        __syncthreads();   // guard all smem reuse from previous tile

        // ---- stage tokens ----
        for (int r = tid; r < E1_TOK; r += THREADS) {
            int g = r0g - CS1 + r;
            s_tok1[r] = (g >= 0 && g < n) ? t1[g] : -1;
        }
        for (int r = tid; r < E2_TOK; r += THREADS) {
            int g = r0g - CS2 + r;
            s_tok2[r] = (g >= 0 && g < n) ? t2[g] : -1;
        }
        __syncthreads();

        // ---- gather embeddings (float2 granularity: 5 per token) ----
        for (int e = tid; e < E1_TOK * 5; e += THREADS) {
            int r = e / 5, q = e - r * 5;
            int tok = s_tok1[r];
            float2 v = (tok >= 0) ? T1f2[tok * 5 + q] : make_float2(0.0f, 0.0f);
            s_e1[r * EPAD + 2*q]     = v.x;
            s_e1[r * EPAD + 2*q + 1] = v.y;
        }
        for (int e = tid; e < E2_TOK * 5; e += THREADS) {
            int r = e / 5, q = e - r * 5;
            int tok = s_tok2[r];
            float2 v = (tok >= 0) ? T2f2[tok * 5 + q] : make_float2(0.0f, 0.0f);
            s_e2[r * EPAD + 2*q]     = v.x;
            s_e2[r * EPAD + 2*q + 1] = v.y;
        }
        __syncthreads();

        // ---- x build (pairwise, low register pressure) + A write ----
        {
            int lo1 = max(i - CS1, 0), hi1 = min(i + CS1 + 1, n);
            int lo2 = max(i - CS2, 0), hi2 = min(i + CS2 + 1, n);
            float inv1 = __fdividef(1.0f, (float)max(hi1 - lo1, 1));
            float inv2 = __fdividef(1.0f, (float)max(hi2 - lo2, 1));
            char* rowh = s_Ahi + tid * SA;
            char* rowl = s_Alo + tid * SA;

            #pragma unroll
            for (int q = 0; q < 5; q++) {        // e1 features 0..9
                float sa = 0.0f, sb = 0.0f;
                #pragma unroll
                for (int w = 0; w < 3; w++) {
                    sa += s_e1[(tid + w) * EPAD + 2*q];
                    sb += s_e1[(tid + w) * EPAD + 2*q + 1];
                }
                uint32_t hi, lo;
                split_pair(sa * inv1, sb * inv1, hi, lo);
                *reinterpret_cast<uint32_t*>(rowh + 4*q) = hi;
                *reinterpret_cast<uint32_t*>(rowl + 4*q) = lo;
            }
            #pragma unroll
            for (int q = 0; q < 5; q++) {        // e2 features 10..19
                float sa = 0.0f, sb = 0.0f;
                #pragma unroll
                for (int w = 0; w < 7; w++) {
                    sa += s_e2[(tid + w) * EPAD + 2*q];
                    sb += s_e2[(tid + w) * EPAD + 2*q + 1];
                }
                uint32_t hi, lo;
                split_pair(sa * inv2, sb * inv2, hi, lo);
                *reinterpret_cast<uint32_t*>(rowh + 4*(5 + q)) = hi;
                *reinterpret_cast<uint32_t*>(rowl + 4*(5 + q)) = lo;
            }
            if (i < n) {                          // numeric features 20..35
                const float4* nf = reinterpret_cast<const float4*>(numf) + (size_t)i * (NUMF / 4);
                #pragma unroll
                for (int q4 = 0; q4 < 4; q4++) {
                    float4 v = nf[q4];
                    uint32_t hi, lo;
                    split_pair(v.x, v.y, hi, lo);
                    *reinterpret_cast<uint32_t*>(rowh + 4*(10 + 2*q4)) = hi;
                    *reinterpret_cast<uint32_t*>(rowl + 4*(10 + 2*q4)) = lo;
                    split_pair(v.z, v.w, hi, lo);
                    *reinterpret_cast<uint32_t*>(rowh + 4*(11 + 2*q4)) = hi;
                    *reinterpret_cast<uint32_t*>(rowl + 4*(11 + 2*q4)) = lo;
                }
            } else {
                #pragma unroll
                for (int q = 10; q < 18; q++) {
                    *reinterpret_cast<uint32_t*>(rowh + 4*q) = 0u;
                    *reinterpret_cast<uint32_t*>(rowl + 4*q) = 0u;
                }
            }
            // bias pair (1.0, 0.0) at k=36,37 ; zero pair k=38,39
            *reinterpret_cast<uint32_t*>(rowh + 4*18) = 0x00003F80u; // bf16(1.0), bf16(0)
            *reinterpret_cast<uint32_t*>(rowl + 4*18) = 0u;
            *reinterpret_cast<uint32_t*>(rowh + 4*19) = 0u;
            *reinterpret_cast<uint32_t*>(rowl + 4*19) = 0u;
        }
        __syncthreads();

        // ---- MMA over 8 m-tiles: K-steps 2x k16 + 1x k8 ----
        #pragma unroll
        for (int mt = 0; mt < 8; mt++) {
            float Dacc[4][4];
            #pragma unroll
            for (int j = 0; j < 4; j++) {
                Dacc[j][0] = 0.f; Dacc[j][1] = 0.f; Dacc[j][2] = 0.f; Dacc[j][3] = 0.f;
            }
            const int rb = mt * 16 + arow;
            const char* r0h = s_Ahi + rb * SA;
            const char* r8h = s_Ahi + (rb + 8) * SA;
            const char* r0l = s_Alo + rb * SA;
            const char* r8l = s_Alo + (rb + 8) * SA;

            #pragma unroll
            for (int s = 0; s < 2; s++) {
                const int cb = s * 32 + acol;
                uint32_t ah0 = *(const uint32_t*)(r0h + cb);
                uint32_t ah1 = *(const uint32_t*)(r8h + cb);
                uint32_t ah2 = *(const uint32_t*)(r0h + cb + 16);
                uint32_t ah3 = *(const uint32_t*)(r8h + cb + 16);
                uint32_t al0 = *(const uint32_t*)(r0l + cb);
                uint32_t al1 = *(const uint32_t*)(r8l + cb);
                uint32_t al2 = *(const uint32_t*)(r0l + cb + 16);
                uint32_t al3 = *(const uint32_t*)(r8l + cb + 16);
                #pragma unroll
                for (int j = 0; j < 4; j++)
                    mma16(Dacc[j], ah0, ah1, ah2, ah3, Bhi[j][2*s], Bhi[j][2*s + 1]);
                #pragma unroll
                for (int j = 0; j < 4; j++)
                    mma16(Dacc[j], ah0, ah1, ah2, ah3, Blo[j][2*s], Blo[j][2*s + 1]);
                #pragma unroll
                for (int j = 0; j < 4; j++)
                    mma16(Dacc[j], al0, al1, al2, al3, Bhi[j][2*s], Bhi[j][2*s + 1]);
            }
            {   // k8 step covering k=32..39 (bias at 36)
                const int cb = 64 + acol;
                uint32_t ah0 = *(const uint32_t*)(r0h + cb);
                uint32_t ah1 = *(const uint32_t*)(r8h + cb);
                uint32_t al0 = *(const uint32_t*)(r0l + cb);
                uint32_t al1 = *(const uint32_t*)(r8l + cb);
                #pragma unroll
                for (int j = 0; j < 4; j++) mma8(Dacc[j], ah0, ah1, Bhi[j][4]);
                #pragma unroll
                for (int j = 0; j < 4; j++) mma8(Dacc[j], ah0, ah1, Blo[j][4]);
                #pragma unroll
                for (int j = 0; j < 4; j++) mma8(Dacc[j], al0, al1, Bhi[j][4]);
            }

            // epilogue: relu + dot with w2 over this warp's 32 columns
            float p0 = 0.0f, p1 = 0.0f;
            #pragma unroll
            for (int j = 0; j < 4; j++) {
                p0 = fmaf(fmaxf(Dacc[j][0], 0.f), w2r[j][0], p0);
                p0 = fmaf(fmaxf(Dacc[j][1], 0.f), w2r[j][1], p0);
                p1 = fmaf(fmaxf(Dacc[j][2], 0.f), w2r[j][0], p1);
                p1 = fmaf(fmaxf(Dacc[j][3], 0.f), w2r[j][1], p1);
            }
            p0 += __shfl_xor_sync(0xFFFFFFFF, p0, 1);
            p0 += __shfl_xor_sync(0xFFFFFFFF, p0, 2);
            p1 += __shfl_xor_sync(0xFFFFFFFF, p1, 1);
            p1 += __shfl_xor_sync(0xFFFFFFFF, p1, 2);
            if ((lane & 3) == 0) {
                s_part[wid][rb]     = p0;
                s_part[wid][rb + 8] = p1;
            }
        }
        __syncthreads();

        // ---- final reduce + sigmoid + store ----
        if (i < n) {
            float s = s_part[0][tid] + s_part[1][tid] + s_part[2][tid] + s_part[3][tid] + b2v;
            out[i] = __fdividef(1.0f, 1.0f + __expf(-s));
        }
    }
}

extern "C" void kernel_launch(void* const* d_in, const int* in_sizes, int n_in,
                              void* d_out, int out_size) {
    const int*   t1   = (const int*)d_in[0];
    const int*   t2   = (const int*)d_in[1];
    const float* numf = (const float*)d_in[2];
    const float* T1   = (const float*)d_in[3];
    const float* T2   = (const float*)d_in[4];
    const float* W1   = (const float*)d_in[5];
    const float* b1   = (const float*)d_in[6];
    const float* W2   = (const float*)d_in[7];
    const float* b2   = (const float*)d_in[8];
    float* out = (float*)d_out;

    int n = in_sizes[0];
    int nTiles = (n + TILE_M - 1) / TILE_M;
    int grid = 148 * 5;
    if (grid > nTiles) grid = nTiles;
    wordemb_mma_gs_kernel<<<grid, THREADS>>>(t1, t2, numf, T1, T2, W1, b1, W2, b2, out, n, nTiles);
}